// round 5
// baseline (speedup 1.0000x reference)
#include <cuda_runtime.h>
#include <cuda_fp16.h>
#include <math_constants.h>
#include <mma.h>

using namespace nvcuda;

#define N_NODES 100000
#define E_EDGES 1600000
#define DIM 128
#define BM 64              // GEMM row tile
#define LDSROW 132         // padded smem row stride (floats): 528B, 16B aligned
#define NEG_SLOPE 0.01f
#define NB_SCAN 98         // ceil(100000/1024)

// ---------------- device scratch (zero-initialized; g_cnt re-zeroed by agg) ----------------
__device__ __half g_h16[N_NODES * DIM];  // node features after linear (fp16, gather-only)
__device__ float g_s[N_NODES];           // per-node leaky-relu score
__device__ float g_Wt[DIM * DIM];        // Wt[k][o] = W[o][k]*mask[k]
__device__ float g_w2[DIM];              // mask ⊙ (W^T @ attn)
__device__ int   g_cnt[N_NODES];
__device__ int   g_off[N_NODES];
__device__ int   g_cur[N_NODES];
__device__ int   g_csrc[E_EDGES];
__device__ int   g_bsum[128];

// ---------------- count in-degrees (g_cnt zeroed by previous agg / static init) ----------------
__global__ void count_kernel(const int* __restrict__ dst) {
    int e4 = blockIdx.x * blockDim.x + threadIdx.x;
    if (e4 < E_EDGES / 4) {
        int4 d = reinterpret_cast<const int4*>(dst)[e4];
        atomicAdd(&g_cnt[d.x], 1);
        atomicAdd(&g_cnt[d.y], 1);
        atomicAdd(&g_cnt[d.z], 1);
        atomicAdd(&g_cnt[d.w], 1);
    }
}

// ---------------- fold mask into W (transpose) + build w2 ----------------
__global__ void prep_kernel(const float* __restrict__ W, const float* __restrict__ mask,
                            const float* __restrict__ attn) {
    int i = threadIdx.x;                 // k index 0..127
    float mi = mask[i];
    float acc = 0.f;
#pragma unroll 4
    for (int o = 0; o < DIM; ++o) {
        float w = W[o * DIM + i];        // coalesced over i
        g_Wt[i * DIM + o] = w * mi;
        acc = fmaf(w, attn[o], acc);
    }
    g_w2[i] = mi * acc;
}

// ---------------- block-local exclusive scan ----------------
__global__ void scan1_kernel() {
    __shared__ int wsum[32];
    int idx  = blockIdx.x * 1024 + threadIdx.x;
    int lane = threadIdx.x & 31, wid = threadIdx.x >> 5;
    int v = (idx < N_NODES) ? g_cnt[idx] : 0;
    int inc = v;
#pragma unroll
    for (int d = 1; d < 32; d <<= 1) {
        int tmp = __shfl_up_sync(0xffffffffu, inc, d);
        if (lane >= d) inc += tmp;
    }
    if (lane == 31) wsum[wid] = inc;
    __syncthreads();
    if (wid == 0) {
        int wv = wsum[lane];
        int winc = wv;
#pragma unroll
        for (int d = 1; d < 32; d <<= 1) {
            int tmp = __shfl_up_sync(0xffffffffu, winc, d);
            if (lane >= d) winc += tmp;
        }
        wsum[lane] = winc - wv;
        if (lane == 31) g_bsum[blockIdx.x] = winc;
    }
    __syncthreads();
    if (idx < N_NODES) g_off[idx] = inc - v + wsum[wid];
}

// ---------------- tf32 wmma GEMM  h = feat @ Wt  (+ fused s = leaky(feat·w2)) ----------------
// 256 threads, tile 64x128, K=128 staged in smem; 2 CTAs/SM.
__global__ void __launch_bounds__(256, 2) gemm_kernel(const float* __restrict__ feat) {
    extern __shared__ float smem[];
    float* As = smem;                    // [64][LDSROW]
    float* Bs = smem + BM * LDSROW;      // [128][LDSROW]

    const int t    = threadIdx.x;
    const int lane = t & 31;
    const int wid  = t >> 5;
    const int wm   = wid & 1;            // 2 row groups of 32
    const int wn   = wid >> 1;           // 4 col groups of 32
    const int rb   = blockIdx.x * BM;

    // stage Wt -> Bs (128 x 128)
    const float4* wt4 = reinterpret_cast<const float4*>(g_Wt);
#pragma unroll
    for (int it = 0; it < 16; ++it) {
        int idx = t + it * 256;          // 0..4095
        int k = idx >> 5, oq = idx & 31;
        *reinterpret_cast<float4*>(&Bs[k * LDSROW + oq * 4]) = wt4[k * 32 + oq];
    }
    // stage feat tile -> As (64 x 128, row-major)
    const float4* f4 = reinterpret_cast<const float4*>(feat);
#pragma unroll
    for (int it = 0; it < 8; ++it) {
        int idx = t + it * 256;          // 0..2047
        int r = idx >> 5, kq = idx & 31;
        int row = rb + r;
        float4 v = (row < N_NODES) ? f4[row * 32 + kq] : make_float4(0.f, 0.f, 0.f, 0.f);
        *reinterpret_cast<float4*>(&As[r * LDSROW + kq * 4]) = v;
    }
    __syncthreads();

    // fused score from staged tile (exact fp32): one warp per row, 8 rows/pass
    {
        float4 w4 = reinterpret_cast<const float4*>(g_w2)[lane];
#pragma unroll
        for (int it = 0; it < 8; ++it) {
            int r = it * 8 + wid;
            float4 f = *reinterpret_cast<const float4*>(&As[r * LDSROW + lane * 4]);
            float p = f.x * w4.x + f.y * w4.y + f.z * w4.z + f.w * w4.w;
#pragma unroll
            for (int o = 16; o > 0; o >>= 1) p += __shfl_xor_sync(0xffffffffu, p, o);
            if (lane == 0) {
                int row = rb + r;
                if (row < N_NODES) g_s[row] = (p > 0.f) ? p : NEG_SLOPE * p;
            }
        }
    }

    wmma::fragment<wmma::accumulator, 16, 16, 8, float> c[2][2];
#pragma unroll
    for (int i = 0; i < 2; ++i)
#pragma unroll
        for (int j = 0; j < 2; ++j) wmma::fill_fragment(c[i][j], 0.f);

#pragma unroll
    for (int k0 = 0; k0 < DIM; k0 += 8) {
        wmma::fragment<wmma::matrix_a, 16, 16, 8, wmma::precision::tf32, wmma::row_major> a[2];
        wmma::fragment<wmma::matrix_b, 16, 16, 8, wmma::precision::tf32, wmma::row_major> b[2];
#pragma unroll
        for (int i = 0; i < 2; ++i) {
            wmma::load_matrix_sync(a[i], &As[(wm * 32 + i * 16) * LDSROW + k0], LDSROW);
#pragma unroll
            for (int e = 0; e < a[i].num_elements; ++e)
                a[i].x[e] = wmma::__float_to_tf32(a[i].x[e]);
        }
#pragma unroll
        for (int j = 0; j < 2; ++j) {
            wmma::load_matrix_sync(b[j], &Bs[k0 * LDSROW + wn * 32 + j * 16], LDSROW);
#pragma unroll
            for (int e = 0; e < b[j].num_elements; ++e)
                b[j].x[e] = wmma::__float_to_tf32(b[j].x[e]);
        }
#pragma unroll
        for (int i = 0; i < 2; ++i)
#pragma unroll
            for (int j = 0; j < 2; ++j)
                wmma::mma_sync(c[i][j], a[i], b[j], c[i][j]);
    }

    // stage accumulators to smem, then fp16-convert + coalesced write
    __syncthreads();
    float* Cs = smem;                    // [64][LDSROW]
#pragma unroll
    for (int i = 0; i < 2; ++i)
#pragma unroll
        for (int j = 0; j < 2; ++j)
            wmma::store_matrix_sync(&Cs[(wm * 32 + i * 16) * LDSROW + wn * 32 + j * 16],
                                    c[i][j], LDSROW, wmma::mem_row_major);
    __syncthreads();
    uint2* h16 = reinterpret_cast<uint2*>(g_h16);
#pragma unroll
    for (int it = 0; it < 8; ++it) {
        int idx = t + it * 256;
        int r = idx >> 5, kq = idx & 31;
        int row = rb + r;
        if (row < N_NODES) {
            float4 v = *reinterpret_cast<float4*>(&Cs[r * LDSROW + kq * 4]);
            __half2 lo = __floats2half2_rn(v.x, v.y);
            __half2 hi = __floats2half2_rn(v.z, v.w);
            uint2 u;
            u.x = *reinterpret_cast<unsigned*>(&lo);
            u.y = *reinterpret_cast<unsigned*>(&hi);
            h16[row * 32 + kq] = u;
        }
    }
}

// ---------------- scan block sums ----------------
__global__ void scan2_kernel() {
    __shared__ int sm[128];
    int t = threadIdx.x;
    int v = (t < NB_SCAN) ? g_bsum[t] : 0;
    sm[t] = v;
    __syncthreads();
#pragma unroll
    for (int d = 1; d < 128; d <<= 1) {
        int add = (t >= d) ? sm[t - d] : 0;
        __syncthreads();
        sm[t] += add;
        __syncthreads();
    }
    if (t < NB_SCAN) g_bsum[t] = sm[t] - v;
}

// ---------------- add block offsets; init fill cursors ----------------
__global__ void scan3_kernel() {
    int idx = blockIdx.x * blockDim.x + threadIdx.x;
    if (idx < N_NODES) {
        int o = g_off[idx] + g_bsum[idx >> 10];
        g_off[idx] = o;
        g_cur[idx] = o;          // absolute cursor
    }
}

// ---------------- scatter edges into CSR buckets ----------------
__global__ void fill_kernel(const int* __restrict__ src, const int* __restrict__ dst) {
    int e4 = blockIdx.x * blockDim.x + threadIdx.x;
    if (e4 < E_EDGES / 4) {
        int4 s = reinterpret_cast<const int4*>(src)[e4];
        int4 d = reinterpret_cast<const int4*>(dst)[e4];
        g_csrc[atomicAdd(&g_cur[d.x], 1)] = s.x;
        g_csrc[atomicAdd(&g_cur[d.y], 1)] = s.y;
        g_csrc[atomicAdd(&g_cur[d.z], 1)] = s.z;
        g_csrc[atomicAdd(&g_cur[d.w], 1)] = s.w;
    }
}

// ---------------- per-dst softmax + aggregation + relu (unroll-4, fp16 gather) ----------------
__global__ void __launch_bounds__(256) agg_kernel(float* __restrict__ out) {
    int gtid = blockIdx.x * blockDim.x + threadIdx.x;
    int v    = gtid >> 5;
    int lane = gtid & 31;
    if (v >= N_NODES) return;

    int n   = g_cnt[v];
    int beg = g_off[v];
    float4 acc = make_float4(0.f, 0.f, 0.f, 0.f);

    if (n > 0) {
        const uint2* hp = reinterpret_cast<const uint2*>(g_h16);
        float denom = 0.f;
        int i = 0;
        for (; i + 4 <= n; i += 4) {
            int s0 = g_csrc[beg + i];
            int s1 = g_csrc[beg + i + 1];
            int s2 = g_csrc[beg + i + 2];
            int s3 = g_csrc[beg + i + 3];
            float w0 = __expf(g_s[s0]);
            float w1 = __expf(g_s[s1]);
            float w2 = __expf(g_s[s2]);
            float w3 = __expf(g_s[s3]);
            uint2 u0 = hp[s0 * 32 + lane];
            uint2 u1 = hp[s1 * 32 + lane];
            uint2 u2 = hp[s2 * 32 + lane];
            uint2 u3 = hp[s3 * 32 + lane];
            denom += (w0 + w1) + (w2 + w3);
            float2 a0 = __half22float2(*reinterpret_cast<__half2*>(&u0.x));
            float2 b0 = __half22float2(*reinterpret_cast<__half2*>(&u0.y));
            float2 a1 = __half22float2(*reinterpret_cast<__half2*>(&u1.x));
            float2 b1 = __half22float2(*reinterpret_cast<__half2*>(&u1.y));
            float2 a2 = __half22float2(*reinterpret_cast<__half2*>(&u2.x));
            float2 b2 = __half22float2(*reinterpret_cast<__half2*>(&u2.y));
            float2 a3 = __half22float2(*reinterpret_cast<__half2*>(&u3.x));
            float2 b3 = __half22float2(*reinterpret_cast<__half2*>(&u3.y));
            acc.x += (w0 * a0.x + w1 * a1.x) + (w2 * a2.x + w3 * a3.x);
            acc.y += (w0 * a0.y + w1 * a1.y) + (w2 * a2.y + w3 * a3.y);
            acc.z += (w0 * b0.x + w1 * b1.x) + (w2 * b2.x + w3 * b3.x);
            acc.w += (w0 * b0.y + w1 * b1.y) + (w2 * b2.y + w3 * b3.y);
        }
        for (; i < n; ++i) {
            int s0 = g_csrc[beg + i];
            float w0 = __expf(g_s[s0]);
            uint2 u0 = hp[s0 * 32 + lane];
            denom += w0;
            float2 a0 = __half22float2(*reinterpret_cast<__half2*>(&u0.x));
            float2 b0 = __half22float2(*reinterpret_cast<__half2*>(&u0.y));
            acc.x += w0 * a0.x; acc.y += w0 * a0.y;
            acc.z += w0 * b0.x; acc.w += w0 * b0.y;
        }
        float inv = 1.f / denom;
        acc.x *= inv; acc.y *= inv; acc.z *= inv; acc.w *= inv;
        if (lane == 0) g_cnt[v] = 0;   // reset for next invocation (replaces zero_kernel)
    }
    acc.x = fmaxf(acc.x, 0.f); acc.y = fmaxf(acc.y, 0.f);
    acc.z = fmaxf(acc.z, 0.f); acc.w = fmaxf(acc.w, 0.f);
    reinterpret_cast<float4*>(out)[v * 32 + lane] = acc;
}

// ---------------- launch (ordered so gemm is launch index 3 for ncu) ----------------
extern "C" void kernel_launch(void* const* d_in, const int* in_sizes, int n_in,
                              void* d_out, int out_size) {
    const float* feat = (const float*)d_in[0];
    const float* mask = (const float*)d_in[1];
    const float* W    = (const float*)d_in[2];
    const float* attn = (const float*)d_in[3];
    const int*   src  = (const int*)d_in[4];
    const int*   dst  = (const int*)d_in[5];
    float* out = (float*)d_out;

    count_kernel<<<(E_EDGES / 4 + 255) / 256, 256>>>(dst);        // 0
    prep_kernel<<<1, 128>>>(W, mask, attn);                       // 1
    scan1_kernel<<<NB_SCAN, 1024>>>();                            // 2

    const int smemB = (BM + DIM) * LDSROW * (int)sizeof(float);   // 101,376 B
    cudaFuncSetAttribute(gemm_kernel, cudaFuncAttributeMaxDynamicSharedMemorySize, smemB);
    gemm_kernel<<<(N_NODES + BM - 1) / BM, 256, smemB>>>(feat);   // 3  <-- profiled

    scan2_kernel<<<1, 128>>>();                                   // 4
    scan3_kernel<<<(N_NODES + 255) / 256, 256>>>();               // 5
    fill_kernel<<<(E_EDGES / 4 + 255) / 256, 256>>>(src, dst);    // 6
    agg_kernel<<<(N_NODES * 32 + 255) / 256, 256>>>(out);         // 7
}

// round 6
// speedup vs baseline: 1.3212x; 1.3212x over previous
#include <cuda_runtime.h>
#include <cuda_fp16.h>
#include <math_constants.h>
#include <mma.h>

using namespace nvcuda;

#define N_NODES 100000
#define E_EDGES 1600000
#define DIM 128
#define BM 128             // GEMM row tile
#define PADH 136           // smem row stride in halves (272B, 16B aligned)
#define PADF 132           // smem row stride in floats for C staging (528B)
#define NEG_SLOPE 0.01f
#define NB_SCAN 98         // ceil(100000/1024)

// ---------------- device scratch (zero-initialized; g_cnt re-zeroed by agg) ----------------
__device__ __half g_h16[N_NODES * DIM];  // node features after linear (fp16, gather-only)
__device__ float  g_s[N_NODES];          // per-node leaky-relu score (fp32)
__device__ __half g_Wt16[DIM * DIM];     // Wt[k][o] = W[o][k]*mask[k], fp16
__device__ float  g_w2[DIM];             // mask ⊙ (W^T @ attn)
__device__ int    g_cnt[N_NODES];
__device__ int    g_off[N_NODES];
__device__ int    g_cur[N_NODES];
__device__ int    g_csrc[E_EDGES];
__device__ int    g_bsum[128];

// ---------------- count in-degrees ----------------
__global__ void count_kernel(const int* __restrict__ dst) {
    int e4 = blockIdx.x * blockDim.x + threadIdx.x;
    if (e4 < E_EDGES / 4) {
        int4 d = reinterpret_cast<const int4*>(dst)[e4];
        atomicAdd(&g_cnt[d.x], 1);
        atomicAdd(&g_cnt[d.y], 1);
        atomicAdd(&g_cnt[d.z], 1);
        atomicAdd(&g_cnt[d.w], 1);
    }
}

// ---------------- fold mask into W (transpose, fp16) + build w2 (fp32) ----------------
__global__ void prep_kernel(const float* __restrict__ W, const float* __restrict__ mask,
                            const float* __restrict__ attn) {
    int i = threadIdx.x;                 // k index 0..127
    float mi = mask[i];
    float acc = 0.f;
#pragma unroll 4
    for (int o = 0; o < DIM; ++o) {
        float w = W[o * DIM + i];        // coalesced over i
        g_Wt16[i * DIM + o] = __float2half_rn(w * mi);
        acc = fmaf(w, attn[o], acc);
    }
    g_w2[i] = mi * acc;
}

// ---------------- block-local exclusive scan ----------------
__global__ void scan1_kernel() {
    __shared__ int wsum[32];
    int idx  = blockIdx.x * 1024 + threadIdx.x;
    int lane = threadIdx.x & 31, wid = threadIdx.x >> 5;
    int v = (idx < N_NODES) ? g_cnt[idx] : 0;
    int inc = v;
#pragma unroll
    for (int d = 1; d < 32; d <<= 1) {
        int tmp = __shfl_up_sync(0xffffffffu, inc, d);
        if (lane >= d) inc += tmp;
    }
    if (lane == 31) wsum[wid] = inc;
    __syncthreads();
    if (wid == 0) {
        int wv = wsum[lane];
        int winc = wv;
#pragma unroll
        for (int d = 1; d < 32; d <<= 1) {
            int tmp = __shfl_up_sync(0xffffffffu, winc, d);
            if (lane >= d) winc += tmp;
        }
        wsum[lane] = winc - wv;
        if (lane == 31) g_bsum[blockIdx.x] = winc;
    }
    __syncthreads();
    if (idx < N_NODES) g_off[idx] = inc - v + wsum[wid];
}

// ---------------- fp16 wmma GEMM  h = feat @ Wt  (+ exact-fp32 fused score) ----------------
// 256 threads (8 warps: 4 row groups x 2 col groups), tile 128x128, K=128 in smem.
__global__ void __launch_bounds__(256) gemm_kernel(const float* __restrict__ feat) {
    extern __shared__ __half smemh[];
    __half* As = smemh;                  // [128][PADH]
    __half* Bs = smemh + BM * PADH;      // [128][PADH]

    const int t    = threadIdx.x;
    const int lane = t & 31;
    const int wid  = t >> 5;
    const int wm   = wid & 3;            // 4 row groups of 32
    const int wn   = wid >> 2;           // 2 col groups of 64
    const int rb   = blockIdx.x * BM;

    // stage Wt16 -> Bs (uint4 = 8 halves)
    const uint4* wt8 = reinterpret_cast<const uint4*>(g_Wt16);
#pragma unroll
    for (int it = 0; it < 8; ++it) {
        int idx = t + it * 256;          // 0..2047
        int k = idx >> 4, q = idx & 15;
        *reinterpret_cast<uint4*>(&Bs[k * PADH + q * 8]) = wt8[k * 16 + q];
    }

    // stage feat tile -> As (fp16) and compute exact-fp32 score while data is in regs.
    // Warp w stages row (it*8 + w) fully: lane == kq (4 floats per lane).
    const float4* f4 = reinterpret_cast<const float4*>(feat);
    float4 w4 = reinterpret_cast<const float4*>(g_w2)[lane];
#pragma unroll
    for (int it = 0; it < 16; ++it) {
        int r = it * 8 + wid;
        int row = rb + r;
        float4 v = (row < N_NODES) ? f4[row * 32 + lane] : make_float4(0.f, 0.f, 0.f, 0.f);
        // score partial (exact fp32 on unconverted values)
        float p = v.x * w4.x + v.y * w4.y + v.z * w4.z + v.w * w4.w;
#pragma unroll
        for (int o = 16; o > 0; o >>= 1) p += __shfl_xor_sync(0xffffffffu, p, o);
        if (lane == 0 && row < N_NODES) g_s[row] = (p > 0.f) ? p : NEG_SLOPE * p;
        // fp16 convert + store
        __half2 lo = __floats2half2_rn(v.x, v.y);
        __half2 hi = __floats2half2_rn(v.z, v.w);
        uint2 u;
        u.x = *reinterpret_cast<unsigned*>(&lo);
        u.y = *reinterpret_cast<unsigned*>(&hi);
        *reinterpret_cast<uint2*>(&As[r * PADH + lane * 4]) = u;
    }
    __syncthreads();

    wmma::fragment<wmma::accumulator, 16, 16, 16, float> c[2][4];
#pragma unroll
    for (int i = 0; i < 2; ++i)
#pragma unroll
        for (int j = 0; j < 4; ++j) wmma::fill_fragment(c[i][j], 0.f);

#pragma unroll
    for (int k0 = 0; k0 < DIM; k0 += 16) {
        wmma::fragment<wmma::matrix_a, 16, 16, 16, __half, wmma::row_major> a[2];
        wmma::fragment<wmma::matrix_b, 16, 16, 16, __half, wmma::row_major> b[4];
#pragma unroll
        for (int i = 0; i < 2; ++i)
            wmma::load_matrix_sync(a[i], &As[(wm * 32 + i * 16) * PADH + k0], PADH);
#pragma unroll
        for (int j = 0; j < 4; ++j)
            wmma::load_matrix_sync(b[j], &Bs[k0 * PADH + wn * 64 + j * 16], PADH);
#pragma unroll
        for (int i = 0; i < 2; ++i)
#pragma unroll
            for (int j = 0; j < 4; ++j)
                wmma::mma_sync(c[i][j], a[i], b[j], c[i][j]);
    }

    // stage fp32 accumulators to smem, then fp16-convert + coalesced write
    __syncthreads();
    float* Cs = reinterpret_cast<float*>(smemh);   // [128][PADF] (67.6KB <= 69.6KB)
#pragma unroll
    for (int i = 0; i < 2; ++i)
#pragma unroll
        for (int j = 0; j < 4; ++j)
            wmma::store_matrix_sync(&Cs[(wm * 32 + i * 16) * PADF + wn * 64 + j * 16],
                                    c[i][j], PADF, wmma::mem_row_major);
    __syncthreads();
    uint2* h16 = reinterpret_cast<uint2*>(g_h16);
#pragma unroll
    for (int it = 0; it < 16; ++it) {
        int idx = t + it * 256;
        int r = idx >> 5, kq = idx & 31;
        int row = rb + r;
        if (row < N_NODES) {
            float4 v = *reinterpret_cast<float4*>(&Cs[r * PADF + kq * 4]);
            __half2 lo = __floats2half2_rn(v.x, v.y);
            __half2 hi = __floats2half2_rn(v.z, v.w);
            uint2 u;
            u.x = *reinterpret_cast<unsigned*>(&lo);
            u.y = *reinterpret_cast<unsigned*>(&hi);
            h16[row * 32 + kq] = u;
        }
    }
}

// ---------------- scan block sums ----------------
__global__ void scan2_kernel() {
    __shared__ int sm[128];
    int t = threadIdx.x;
    int v = (t < NB_SCAN) ? g_bsum[t] : 0;
    sm[t] = v;
    __syncthreads();
#pragma unroll
    for (int d = 1; d < 128; d <<= 1) {
        int add = (t >= d) ? sm[t - d] : 0;
        __syncthreads();
        sm[t] += add;
        __syncthreads();
    }
    if (t < NB_SCAN) g_bsum[t] = sm[t] - v;
}

// ---------------- add block offsets; init fill cursors ----------------
__global__ void scan3_kernel() {
    int idx = blockIdx.x * blockDim.x + threadIdx.x;
    if (idx < N_NODES) {
        int o = g_off[idx] + g_bsum[idx >> 10];
        g_off[idx] = o;
        g_cur[idx] = o;          // absolute cursor
    }
}

// ---------------- scatter edges into CSR buckets ----------------
__global__ void fill_kernel(const int* __restrict__ src, const int* __restrict__ dst) {
    int e4 = blockIdx.x * blockDim.x + threadIdx.x;
    if (e4 < E_EDGES / 4) {
        int4 s = reinterpret_cast<const int4*>(src)[e4];
        int4 d = reinterpret_cast<const int4*>(dst)[e4];
        g_csrc[atomicAdd(&g_cur[d.x], 1)] = s.x;
        g_csrc[atomicAdd(&g_cur[d.y], 1)] = s.y;
        g_csrc[atomicAdd(&g_cur[d.z], 1)] = s.z;
        g_csrc[atomicAdd(&g_cur[d.w], 1)] = s.w;
    }
}

// ---------------- per-dst softmax + aggregation + relu (unroll-4, fp16 gather) ----------------
__global__ void __launch_bounds__(256) agg_kernel(float* __restrict__ out) {
    int gtid = blockIdx.x * blockDim.x + threadIdx.x;
    int v    = gtid >> 5;
    int lane = gtid & 31;
    if (v >= N_NODES) return;

    int n   = g_cnt[v];
    int beg = g_off[v];
    float4 acc = make_float4(0.f, 0.f, 0.f, 0.f);

    if (n > 0) {
        const uint2* hp = reinterpret_cast<const uint2*>(g_h16);
        float denom = 0.f;
        int i = 0;
        for (; i + 4 <= n; i += 4) {
            int s0 = g_csrc[beg + i];
            int s1 = g_csrc[beg + i + 1];
            int s2 = g_csrc[beg + i + 2];
            int s3 = g_csrc[beg + i + 3];
            float w0 = __expf(g_s[s0]);
            float w1 = __expf(g_s[s1]);
            float w2 = __expf(g_s[s2]);
            float w3 = __expf(g_s[s3]);
            uint2 u0 = hp[s0 * 32 + lane];
            uint2 u1 = hp[s1 * 32 + lane];
            uint2 u2 = hp[s2 * 32 + lane];
            uint2 u3 = hp[s3 * 32 + lane];
            denom += (w0 + w1) + (w2 + w3);
            float2 a0 = __half22float2(*reinterpret_cast<__half2*>(&u0.x));
            float2 b0 = __half22float2(*reinterpret_cast<__half2*>(&u0.y));
            float2 a1 = __half22float2(*reinterpret_cast<__half2*>(&u1.x));
            float2 b1 = __half22float2(*reinterpret_cast<__half2*>(&u1.y));
            float2 a2 = __half22float2(*reinterpret_cast<__half2*>(&u2.x));
            float2 b2 = __half22float2(*reinterpret_cast<__half2*>(&u2.y));
            float2 a3 = __half22float2(*reinterpret_cast<__half2*>(&u3.x));
            float2 b3 = __half22float2(*reinterpret_cast<__half2*>(&u3.y));
            acc.x += (w0 * a0.x + w1 * a1.x) + (w2 * a2.x + w3 * a3.x);
            acc.y += (w0 * a0.y + w1 * a1.y) + (w2 * a2.y + w3 * a3.y);
            acc.z += (w0 * b0.x + w1 * b1.x) + (w2 * b2.x + w3 * b3.x);
            acc.w += (w0 * b0.y + w1 * b1.y) + (w2 * b2.y + w3 * b3.y);
        }
        for (; i < n; ++i) {
            int s0 = g_csrc[beg + i];
            float w0 = __expf(g_s[s0]);
            uint2 u0 = hp[s0 * 32 + lane];
            denom += w0;
            float2 a0 = __half22float2(*reinterpret_cast<__half2*>(&u0.x));
            float2 b0 = __half22float2(*reinterpret_cast<__half2*>(&u0.y));
            acc.x += w0 * a0.x; acc.y += w0 * a0.y;
            acc.z += w0 * b0.x; acc.w += w0 * b0.y;
        }
        float inv = 1.f / denom;
        acc.x *= inv; acc.y *= inv; acc.z *= inv; acc.w *= inv;
        if (lane == 0) g_cnt[v] = 0;   // reset for next replay (replaces zero_kernel)
    }
    acc.x = fmaxf(acc.x, 0.f); acc.y = fmaxf(acc.y, 0.f);
    acc.z = fmaxf(acc.z, 0.f); acc.w = fmaxf(acc.w, 0.f);
    reinterpret_cast<float4*>(out)[v * 32 + lane] = acc;
}

// ---------------- launch (gemm kept at index 3 for ncu) ----------------
extern "C" void kernel_launch(void* const* d_in, const int* in_sizes, int n_in,
                              void* d_out, int out_size) {
    const float* feat = (const float*)d_in[0];
    const float* mask = (const float*)d_in[1];
    const float* W    = (const float*)d_in[2];
    const float* attn = (const float*)d_in[3];
    const int*   src  = (const int*)d_in[4];
    const int*   dst  = (const int*)d_in[5];
    float* out = (float*)d_out;

    count_kernel<<<(E_EDGES / 4 + 255) / 256, 256>>>(dst);        // 0
    prep_kernel<<<1, 128>>>(W, mask, attn);                       // 1
    scan1_kernel<<<NB_SCAN, 1024>>>();                            // 2

    const int smemB = 2 * BM * PADH * (int)sizeof(__half);        // 69,632 B
    cudaFuncSetAttribute(gemm_kernel, cudaFuncAttributeMaxDynamicSharedMemorySize, smemB);
    gemm_kernel<<<(N_NODES + BM - 1) / BM, 256, smemB>>>(feat);   // 3  <-- profiled

    scan2_kernel<<<1, 128>>>();                                   // 4
    scan3_kernel<<<(N_NODES + 255) / 256, 256>>>();               // 5
    fill_kernel<<<(E_EDGES / 4 + 255) / 256, 256>>>(src, dst);    // 6
    agg_kernel<<<(N_NODES * 32 + 255) / 256, 256>>>(out);         // 7
}